// round 15
// baseline (speedup 1.0000x reference)
#include <cuda_runtime.h>

#define L_ 2048
#define E_ 256
#define H2_ 256
#define H4_ 1024
#define T_ 6
#define START_ 4
#define STOP_ 5
#define NEG_ (-10000.0f)
#define NEGI_ (-1.0e30f)
#define NCHUNK_ 128
#define CLEN_ (L_ / NCHUNK_)   // 16

// Scratch (static __device__ arrays: allocation-free per harness rules)
__device__ float g_pre[2][L_][H4_];    // 16 MB: input projections per direction
__device__ float g_h[2][L_][H2_];      // 4 MB: hidden states (position-indexed)
__device__ float g_feats[L_][T_];      // 48 KB: emission scores
__device__ float g_mats[NCHUNK_][40];  // CRF chunk matrices (6x6, padded)

__device__ __forceinline__ void fma2(unsigned long long& d,
                                     unsigned long long a, unsigned long long b) {
    asm("fma.rn.f32x2 %0, %1, %2, %0;" : "+l"(d) : "l"(a), "l"(b));
}
__device__ __forceinline__ float lo32(unsigned long long v) {
    return __uint_as_float((unsigned)(v & 0xffffffffull));
}
__device__ __forceinline__ float hi32(unsigned long long v) {
    return __uint_as_float((unsigned)(v >> 32));
}
__device__ __forceinline__ float tanh_ap(float x) {
    float r; asm("tanh.approx.f32 %0, %1;" : "=f"(r) : "f"(x)); return r;
}
// cta-scope acquire (sufficient: async-proxy data lands in our own smem and
// completion is signaled on our local mbarrier).
__device__ __forceinline__ void mbar_wait(unsigned addr, unsigned ph) {
    unsigned done = 0;
    do {
        asm volatile("{\n\t.reg .pred p;\n\t"
            "mbarrier.try_wait.parity.acquire.cta.shared::cta.b64 p, [%1], %2, 0x989680;\n\t"
            "selp.b32 %0, 1, 0, p;\n\t}"
            : "=r"(done) : "r"(addr), "r"(ph) : "memory");
    } while (!done);
}

// ---------------------------------------------------------------------------
// Kernel 0: no-op (ncu launch-index steering keeps lstm_kernel profiled).
// ---------------------------------------------------------------------------
__global__ void noop_kernel() {}

// ---------------------------------------------------------------------------
// Kernel 1: pre[d][t][n] = sum_k embed[sent[t']][k] * Wih_d[n][k] + bih[n] + bhh[n]
// ---------------------------------------------------------------------------
__global__ __launch_bounds__(256) void gemm_pre_kernel(
    const int* __restrict__ sent, const float* __restrict__ embed,
    const float* __restrict__ WihF, const float* __restrict__ bihF, const float* __restrict__ bhhF,
    const float* __restrict__ WihB, const float* __restrict__ bihB, const float* __restrict__ bhhB)
{
    const int d = blockIdx.z;
    const float* __restrict__ Wih = d ? WihB : WihF;
    const float* __restrict__ bih = d ? bihB : bihF;
    const float* __restrict__ bhh = d ? bhhB : bhhF;

    __shared__ __align__(16) float As[16][64];   // [k][m]
    __shared__ __align__(16) float Bs[16][64];   // [k][n]

    const int t0 = blockIdx.x * 64;
    const int n0 = blockIdx.y * 64;
    const int tid = threadIdx.x;
    const int tm = (tid & 15) * 4;
    const int tn = (tid >> 4) * 4;
    const int am = tid >> 2;         // 0..63
    const int ak = (tid & 3) * 4;    // 0,4,8,12

    const int tg = t0 + am;
    const int tp = d ? (L_ - 1 - tg) : tg;
    const float* arow = embed + (size_t)sent[tp] * E_;
    const float* brow = Wih + (size_t)(n0 + am) * E_;

    unsigned long long acc2[4][2];
    #pragma unroll
    for (int i = 0; i < 4; i++) { acc2[i][0] = 0ull; acc2[i][1] = 0ull; }

    for (int k0 = 0; k0 < E_; k0 += 16) {
        float4 av = *(const float4*)(arow + k0 + ak);
        float4 bv = *(const float4*)(brow + k0 + ak);
        __syncthreads();
        As[ak + 0][am] = av.x; As[ak + 1][am] = av.y;
        As[ak + 2][am] = av.z; As[ak + 3][am] = av.w;
        Bs[ak + 0][am] = bv.x; Bs[ak + 1][am] = bv.y;
        Bs[ak + 2][am] = bv.z; Bs[ak + 3][am] = bv.w;
        __syncthreads();
        #pragma unroll
        for (int kk = 0; kk < 16; kk++) {
            float a4[4];
            *(float4*)a4 = *(const float4*)&As[kk][tm];
            ulonglong2 b2 = *(const ulonglong2*)&Bs[kk][tn];
            #pragma unroll
            for (int i = 0; i < 4; i++) {
                unsigned long long asp;
                asm("mov.b64 %0, {%1, %1};" : "=l"(asp) : "f"(a4[i]));
                fma2(acc2[i][0], asp, b2.x);
                fma2(acc2[i][1], asp, b2.y);
            }
        }
    }
    #pragma unroll
    for (int i = 0; i < 4; i++) {
        float r[4] = { lo32(acc2[i][0]), hi32(acc2[i][0]),
                       lo32(acc2[i][1]), hi32(acc2[i][1]) };
        #pragma unroll
        for (int j = 0; j < 4; j++) {
            int n = n0 + tn + j;
            g_pre[d][t0 + tm + i][n] = r[j] + bih[n] + bhh[n];
        }
    }
}

// ---------------------------------------------------------------------------
// Kernel 2: LSTM recurrence, 8-CTA cluster per direction (round-14 structure,
// best measured). CHANGE this round: the h exchange sends HALF the messages
// at the same byte count -- lanes with even element ((l&8)==0, 16/warp) fetch
// their odd partner's h via one shfl.xor(8) and ship the contiguous pair
// (e, e+1) as a single 8-byte st.async.v2.b32 (128 msgs x 8 B per dest per
// phase; expect_tx stays 1024 B, addresses unchanged).
// ---------------------------------------------------------------------------
__global__ void __cluster_dims__(8, 1, 1) __launch_bounds__(256, 1)
lstm_kernel(const float* __restrict__ WhhF, const float* __restrict__ WhhB,
            const float* __restrict__ h0, const float* __restrict__ c0)
{
    __shared__ __align__(16) float h_sm[2][H2_];
    __shared__ __align__(8) unsigned long long mbar[2];

    const int d = blockIdx.y;
    unsigned rank;
    asm("mov.u32 %0, %%cluster_ctarank;" : "=r"(rank));

    const int tid = threadIdx.x;
    const int w = tid >> 5;          // warp 0..7
    const int l = tid & 31;          // lane
    const int ri = l >> 1;           // row-in-warp 0..15
    const int half = l & 1;          // column half
    const int q = ri >> 2;           // own gate: 0=i 1=f 2=g 3=o (= l>>3)
    const int i4 = ri & 3;           // own element within warp's 4 h-values
    const int e = l >> 3;            // element this lane FINISHES (c/h owner)
    const int grow = q * 256 + (int)rank * 32 + w * 4 + i4;   // global W row
    const float* __restrict__ Whh = d ? WhhB : WhhF;

    // Weights: 128 floats per thread = 64 packed f32x2 register pairs
    unsigned long long w2[64];
    {
        const float* wrow = Whh + (size_t)grow * H2_ + half * 128;
        #pragma unroll
        for (int i = 0; i < 32; i++) {
            ulonglong2 v = *(const ulonglong2*)(wrow + 4 * i);
            w2[2 * i] = v.x; w2[2 * i + 1] = v.y;
        }
    }

    const unsigned mb0 = (unsigned)__cvta_generic_to_shared(&mbar[0]);
    const unsigned mb1 = (unsigned)__cvta_generic_to_shared(&mbar[1]);
    if (tid == 0) {
        asm volatile("mbarrier.init.shared.b64 [%0], %1;" :: "r"(mb0), "r"(1) : "memory");
        asm volatile("mbarrier.init.shared.b64 [%0], %1;" :: "r"(mb1), "r"(1) : "memory");
        // pre-post phase 0 of both barriers (stores from steps 0 and 1)
        asm volatile("mbarrier.arrive.expect_tx.shared.b64 _, [%0], %1;" :: "r"(mb1), "r"(1024) : "memory");
        asm volatile("mbarrier.arrive.expect_tx.shared.b64 _, [%0], %1;" :: "r"(mb0), "r"(1024) : "memory");
    }
    h_sm[0][tid] = h0[d * H2_ + tid];
    const int hbase = (int)rank * 32 + w * 4;
    float cst = c0[d * H2_ + hbase + e];     // c-state for element e (8x repl)
    __syncthreads();
    // barrier init + pre-posts must be cluster-visible before any peer st.async
    asm volatile("barrier.cluster.arrive.aligned;" ::: "memory");
    asm volatile("barrier.cluster.wait.aligned;"   ::: "memory");

    const float* __restrict__ pre = &g_pre[d][0][0];
    const unsigned hs0 = (unsigned)__cvta_generic_to_shared(&h_sm[0][hbase]);
    const unsigned hs1 = (unsigned)__cvta_generic_to_shared(&h_sm[1][hbase]);
    // activation constants: g-gate (q==2) uses tanh(z); others 0.5+0.5*tanh(z/2)
    const float kmul = (q == 2) ? 1.f : 0.5f;
    const float kscale = (q == 2) ? 1.f : 0.5f;
    const float kaff = (q == 2) ? 0.f : 0.5f;
    unsigned ph0 = 0, ph1 = 0;

    // gate-gather shfl sources for element e: lanes q'*8 + 2e
    const int srcI = 2 * e;
    // hoisted per-lane remote addresses: dest CTA = l&7, slot = element e
    // (senders have even e -> byte offset e*4 in {0,8}, 8B-aligned for v2)
    const int dl = l & 7;
    unsigned ra0, ra1, rb0, rb1;
    asm("mapa.shared::cluster.u32 %0, %1, %2;" : "=r"(ra0) : "r"(hs0 + e * 4u), "r"(dl));
    asm("mapa.shared::cluster.u32 %0, %1, %2;" : "=r"(ra1) : "r"(hs1 + e * 4u), "r"(dl));
    asm("mapa.shared::cluster.u32 %0, %1, %2;" : "=r"(rb0) : "r"(mb0), "r"(dl));
    asm("mapa.shared::cluster.u32 %0, %1, %2;" : "=r"(rb1) : "r"(mb1), "r"(dl));

    const bool reposter = (w == 0 && l == 0);
    const bool stg = (dl == 0);
    const int sender_bit = l & 8;    // 0 -> this lane sends the (e, e+1) pair

    // one step, compile-time buffer parity
#define LSTM_STEP(T, BUF, MBC, PHC, RA_NEXT, RB_NEXT)                          \
    {                                                                          \
        float p = __ldg(pre + (size_t)(T) * H4_ + grow);                       \
        if ((T) > 0) {                                                         \
            mbar_wait(MBC, PHC); PHC ^= 1;                                     \
            if (reposter && (T) <= L_ - 3) {                                   \
                asm volatile("mbarrier.arrive.expect_tx.shared.b64 _, [%0], %1;" \
                             :: "r"(MBC), "r"(1024) : "memory");               \
            }                                                                  \
        }                                                                      \
        const float* hb = h_sm[BUF] + half * 128;                              \
        unsigned long long a0 = 0, a1 = 0, a2 = 0, a3 = 0;                     \
        _Pragma("unroll")                                                      \
        for (int i = 0; i < 16; i++) {                                         \
            ulonglong2 hv0 = *(const ulonglong2*)(hb + 8 * i);                 \
            ulonglong2 hv1 = *(const ulonglong2*)(hb + 8 * i + 4);             \
            fma2(a0, w2[4 * i + 0], hv0.x);                                    \
            fma2(a1, w2[4 * i + 1], hv0.y);                                    \
            fma2(a2, w2[4 * i + 2], hv1.x);                                    \
            fma2(a3, w2[4 * i + 3], hv1.y);                                    \
        }                                                                      \
        float s = (lo32(a0) + hi32(a0)) + (lo32(a1) + hi32(a1))                \
                + (lo32(a2) + hi32(a2)) + (lo32(a3) + hi32(a3));               \
        s += __shfl_xor_sync(0xffffffffu, s, 1);                               \
        float z = s + p;                                                       \
        float tt = tanh_ap(z * kmul);                                          \
        float act = fmaf(kscale, tt, kaff);                                    \
        float iA = __shfl_sync(0xffffffffu, act, srcI);                        \
        float fA = __shfl_sync(0xffffffffu, act, srcI + 8);                    \
        float gA = __shfl_sync(0xffffffffu, act, srcI + 16);                   \
        float oA = __shfl_sync(0xffffffffu, act, srcI + 24);                   \
        cst = fA * cst + iA * gA;                                              \
        float th = tanh_ap(cst);                                               \
        float h = oA * th;                                                     \
        float hp = __shfl_xor_sync(0xffffffffu, h, 8);  /* partner element */  \
        if ((T) < L_ - 1) {                                                    \
            asm volatile("{\n\t.reg .pred p;\n\t"                              \
                "setp.eq.s32 p, %4, 0;\n\t"                                    \
                "@p st.async.shared::cluster.mbarrier::complete_tx::bytes.v2.b32 " \
                "[%0], {%1,%2}, [%3];\n\t}"                                    \
                :: "r"(RA_NEXT), "r"(__float_as_uint(h)),                      \
                   "r"(__float_as_uint(hp)), "r"(RB_NEXT), "r"(sender_bit)     \
                : "memory");                                                   \
        }                                                                      \
        if (stg) {                                                             \
            const int pos = d ? (L_ - 1 - (T)) : (T);                          \
            g_h[d][pos][hbase + e] = h;                                        \
        }                                                                      \
    }

    for (int t = 0; t < L_; t += 2) {
        LSTM_STEP(t,     0, mb0, ph0, ra1, rb1)   // even step: read buf 0, feed buf 1
        LSTM_STEP(t + 1, 1, mb1, ph1, ra0, rb0)   // odd step:  read buf 1, feed buf 0
    }
#undef LSTM_STEP

    // all phases fully consumed by the final waits; plain exit sync
    asm volatile("barrier.cluster.arrive.aligned;" ::: "memory");
    asm volatile("barrier.cluster.wait.aligned;"   ::: "memory");
}

// ---------------------------------------------------------------------------
// Kernel 3: feats[p][tag] = concat(hf[p],hb[p]) . W_out[tag] + b_out[tag]
// ---------------------------------------------------------------------------
__global__ __launch_bounds__(256) void feats_kernel(
    const float* __restrict__ Wout, const float* __restrict__ bout)
{
    const int warp = threadIdx.x >> 5, lane = threadIdx.x & 31;
    const int p = blockIdx.x * 8 + warp;
    float x[16];
    #pragma unroll
    for (int i = 0; i < 8; i++) x[i] = g_h[0][p][lane + 32 * i];
    #pragma unroll
    for (int i = 0; i < 8; i++) x[8 + i] = g_h[1][p][lane + 32 * i];
    #pragma unroll
    for (int tag = 0; tag < T_; tag++) {
        const float* wrow = Wout + tag * (2 * H2_);
        float acc = 0.f;
        #pragma unroll
        for (int i = 0; i < 16; i++)
            acc += x[i] * wrow[(i < 8 ? 0 : 256) + lane + 32 * (i & 7)];
        #pragma unroll
        for (int o = 16; o > 0; o >>= 1) acc += __shfl_xor_sync(0xffffffffu, acc, o);
        if (lane == 0) g_feats[p][tag] = acc + bout[tag];
    }
}

// ---------------------------------------------------------------------------
// Kernel 4a: CRF chunk matrices (log-semiring parallel scan, 128 chunks x 16).
// ---------------------------------------------------------------------------
__global__ __launch_bounds__(256) void crf_chunks_kernel(
    const float* __restrict__ trans)
{
    const int warp = threadIdx.x >> 5, lane = threadIdx.x & 31;
    const int wc = blockIdx.x * 8 + warp;     // chunk id 0..127
    const int ln = (lane < T_) ? lane : 0;    // this lane's "next" state n

    float trr[T_];
    #pragma unroll
    for (int k = 0; k < T_; k++) trr[k] = trans[ln * T_ + k];

    float m[T_];
    #pragma unroll
    for (int p = 0; p < T_; p++) m[p] = (ln == p) ? 0.f : NEGI_;

    const float* ff = &g_feats[wc * CLEN_][0];
    for (int s = 0; s < CLEN_; s++) {
        const float emit = ff[s * T_ + ln];
        #pragma unroll
        for (int p = 0; p < T_; p++) {
            float v0 = __shfl_sync(0xffffffffu, m[p], 0) + trr[0];
            float v1 = __shfl_sync(0xffffffffu, m[p], 1) + trr[1];
            float v2 = __shfl_sync(0xffffffffu, m[p], 2) + trr[2];
            float v3 = __shfl_sync(0xffffffffu, m[p], 3) + trr[3];
            float v4 = __shfl_sync(0xffffffffu, m[p], 4) + trr[4];
            float v5 = __shfl_sync(0xffffffffu, m[p], 5) + trr[5];
            float mx = fmaxf(fmaxf(fmaxf(v0, v1), fmaxf(v2, v3)), fmaxf(v4, v5));
            float sum = __expf(v0 - mx) + __expf(v1 - mx) + __expf(v2 - mx)
                      + __expf(v3 - mx) + __expf(v4 - mx) + __expf(v5 - mx);
            m[p] = mx + __logf(sum) + emit;
        }
    }
    if (lane < T_) {
        #pragma unroll
        for (int p = 0; p < T_; p++) g_mats[wc][lane * T_ + p] = m[p];
    }
}

// ---------------------------------------------------------------------------
// Kernel 4b: gold score + fold chunk matrices into fv, final logsumexp.
// ---------------------------------------------------------------------------
__global__ __launch_bounds__(256) void crf_final_kernel(
    const int* __restrict__ tags, const float* __restrict__ trans,
    float* __restrict__ out)
{
    __shared__ float red[256];
    const int tid = threadIdx.x;

    // gold score
    float g = 0.f;
    for (int i = tid; i < L_; i += 256) {
        int cur = tags[i];
        int prev = (i == 0) ? START_ : tags[i - 1];
        g += trans[cur * T_ + prev] + g_feats[i][cur];
    }
    if (tid == 0) g += trans[STOP_ * T_ + tags[L_ - 1]];
    red[tid] = g;
    __syncthreads();
    for (int s = 128; s > 0; s >>= 1) {
        if (tid < s) red[tid] += red[tid + s];
        __syncthreads();
    }

    if (tid < 32) {
        const int ln = (tid < T_) ? tid : 0;
        float fv = (ln == START_) ? 0.f : NEG_;
        for (int c = 0; c < NCHUNK_; c++) {
            float r0 = g_mats[c][ln * T_ + 0], r1 = g_mats[c][ln * T_ + 1];
            float r2 = g_mats[c][ln * T_ + 2], r3 = g_mats[c][ln * T_ + 3];
            float r4 = g_mats[c][ln * T_ + 4], r5 = g_mats[c][ln * T_ + 5];
            float v0 = r0 + __shfl_sync(0xffffffffu, fv, 0);
            float v1 = r1 + __shfl_sync(0xffffffffu, fv, 1);
            float v2 = r2 + __shfl_sync(0xffffffffu, fv, 2);
            float v3 = r3 + __shfl_sync(0xffffffffu, fv, 3);
            float v4 = r4 + __shfl_sync(0xffffffffu, fv, 4);
            float v5 = r5 + __shfl_sync(0xffffffffu, fv, 5);
            float mx = fmaxf(fmaxf(fmaxf(v0, v1), fmaxf(v2, v3)), fmaxf(v4, v5));
            float sum = __expf(v0 - mx) + __expf(v1 - mx) + __expf(v2 - mx)
                      + __expf(v3 - mx) + __expf(v4 - mx) + __expf(v5 - mx);
            fv = mx + __logf(sum);
        }
        // final: logsumexp(fv + trans[STOP])
        float v = fv + trans[STOP_ * T_ + ln];
        if (tid >= T_) v = NEGI_;
        float mx = v;
        #pragma unroll
        for (int o = 4; o > 0; o >>= 1) mx = fmaxf(mx, __shfl_xor_sync(0xffu, mx, o));
        mx = __shfl_sync(0xffffffffu, mx, 0);
        float e = (tid < T_) ? __expf(v - mx) : 0.f;
        #pragma unroll
        for (int o = 4; o > 0; o >>= 1) e += __shfl_xor_sync(0xffu, e, o);
        if (tid == 0) out[0] = mx + __logf(e) - red[0];
    }
}

// ---------------------------------------------------------------------------
extern "C" void kernel_launch(void* const* d_in, const int* in_sizes, int n_in,
                              void* d_out, int out_size)
{
    const int*   sentence = (const int*)d_in[0];
    const int*   tags     = (const int*)d_in[1];
    const float* embed    = (const float*)d_in[2];
    const float* Wih_f    = (const float*)d_in[3];
    const float* Whh_f    = (const float*)d_in[4];
    const float* bih_f    = (const float*)d_in[5];
    const float* bhh_f    = (const float*)d_in[6];
    const float* Wih_b    = (const float*)d_in[7];
    const float* Whh_b    = (const float*)d_in[8];
    const float* bih_b    = (const float*)d_in[9];
    const float* bhh_b    = (const float*)d_in[10];
    const float* h0       = (const float*)d_in[11];
    const float* c0       = (const float*)d_in[12];
    const float* W_out    = (const float*)d_in[13];
    const float* b_out    = (const float*)d_in[14];
    const float* trans    = (const float*)d_in[15];
    float* out = (float*)d_out;

    gemm_pre_kernel<<<dim3(L_ / 64, H4_ / 64, 2), 256>>>(
        sentence, embed, Wih_f, bih_f, bhh_f, Wih_b, bih_b, bhh_b);
    // two no-ops: keeps lstm_kernel at the ncu-captured activity index
    noop_kernel<<<1, 32>>>();
    noop_kernel<<<1, 32>>>();
    lstm_kernel<<<dim3(8, 2), 256>>>(Whh_f, Whh_b, h0, c0);
    feats_kernel<<<L_ / 8, 256>>>(W_out, b_out);
    crf_chunks_kernel<<<NCHUNK_ / 8, 256>>>(trans);
    crf_final_kernel<<<1, 256>>>(tags, trans, out);
}

// round 16
// speedup vs baseline: 1.0384x; 1.0384x over previous
#include <cuda_runtime.h>

#define L_ 2048
#define E_ 256
#define H2_ 256
#define H4_ 1024
#define T_ 6
#define START_ 4
#define STOP_ 5
#define NEG_ (-10000.0f)
#define NEGI_ (-1.0e30f)
#define NCHUNK_ 128
#define CLEN_ (L_ / NCHUNK_)   // 16

// Scratch (static __device__ arrays: allocation-free per harness rules)
__device__ float g_pre[2][L_][H4_];    // 16 MB: input projections per direction
__device__ float g_h[2][L_][H2_];      // 4 MB: hidden states (position-indexed)
__device__ float g_feats[L_][T_];      // 48 KB: emission scores
__device__ float g_mats[NCHUNK_][40];  // CRF chunk matrices (6x6, padded)

__device__ __forceinline__ void fma2(unsigned long long& d,
                                     unsigned long long a, unsigned long long b) {
    asm("fma.rn.f32x2 %0, %1, %2, %0;" : "+l"(d) : "l"(a), "l"(b));
}
__device__ __forceinline__ float lo32(unsigned long long v) {
    return __uint_as_float((unsigned)(v & 0xffffffffull));
}
__device__ __forceinline__ float hi32(unsigned long long v) {
    return __uint_as_float((unsigned)(v >> 32));
}
__device__ __forceinline__ float tanh_ap(float x) {
    float r; asm("tanh.approx.f32 %0, %1;" : "=f"(r) : "f"(x)); return r;
}
// cta-scope acquire (sufficient: async-proxy data lands in our own smem and
// completion is signaled on our local mbarrier).
__device__ __forceinline__ void mbar_wait(unsigned addr, unsigned ph) {
    unsigned done = 0;
    do {
        asm volatile("{\n\t.reg .pred p;\n\t"
            "mbarrier.try_wait.parity.acquire.cta.shared::cta.b64 p, [%1], %2, 0x989680;\n\t"
            "selp.b32 %0, 1, 0, p;\n\t}"
            : "=r"(done) : "r"(addr), "r"(ph) : "memory");
    } while (!done);
}

// ---------------------------------------------------------------------------
// Kernel 1: pre[d][t][n] = sum_k embed[sent[t']][k] * Wih_d[n][k] + bih[n] + bhh[n]
// ---------------------------------------------------------------------------
__global__ __launch_bounds__(256) void gemm_pre_kernel(
    const int* __restrict__ sent, const float* __restrict__ embed,
    const float* __restrict__ WihF, const float* __restrict__ bihF, const float* __restrict__ bhhF,
    const float* __restrict__ WihB, const float* __restrict__ bihB, const float* __restrict__ bhhB)
{
    const int d = blockIdx.z;
    const float* __restrict__ Wih = d ? WihB : WihF;
    const float* __restrict__ bih = d ? bihB : bihF;
    const float* __restrict__ bhh = d ? bhhB : bhhF;

    __shared__ __align__(16) float As[16][64];   // [k][m]
    __shared__ __align__(16) float Bs[16][64];   // [k][n]

    const int t0 = blockIdx.x * 64;
    const int n0 = blockIdx.y * 64;
    const int tid = threadIdx.x;
    const int tm = (tid & 15) * 4;
    const int tn = (tid >> 4) * 4;
    const int am = tid >> 2;         // 0..63
    const int ak = (tid & 3) * 4;    // 0,4,8,12

    const int tg = t0 + am;
    const int tp = d ? (L_ - 1 - tg) : tg;
    const float* arow = embed + (size_t)sent[tp] * E_;
    const float* brow = Wih + (size_t)(n0 + am) * E_;

    unsigned long long acc2[4][2];
    #pragma unroll
    for (int i = 0; i < 4; i++) { acc2[i][0] = 0ull; acc2[i][1] = 0ull; }

    for (int k0 = 0; k0 < E_; k0 += 16) {
        float4 av = *(const float4*)(arow + k0 + ak);
        float4 bv = *(const float4*)(brow + k0 + ak);
        __syncthreads();
        As[ak + 0][am] = av.x; As[ak + 1][am] = av.y;
        As[ak + 2][am] = av.z; As[ak + 3][am] = av.w;
        Bs[ak + 0][am] = bv.x; Bs[ak + 1][am] = bv.y;
        Bs[ak + 2][am] = bv.z; Bs[ak + 3][am] = bv.w;
        __syncthreads();
        #pragma unroll
        for (int kk = 0; kk < 16; kk++) {
            float a4[4];
            *(float4*)a4 = *(const float4*)&As[kk][tm];
            ulonglong2 b2 = *(const ulonglong2*)&Bs[kk][tn];
            #pragma unroll
            for (int i = 0; i < 4; i++) {
                unsigned long long asp;
                asm("mov.b64 %0, {%1, %1};" : "=l"(asp) : "f"(a4[i]));
                fma2(acc2[i][0], asp, b2.x);
                fma2(acc2[i][1], asp, b2.y);
            }
        }
    }
    #pragma unroll
    for (int i = 0; i < 4; i++) {
        float r[4] = { lo32(acc2[i][0]), hi32(acc2[i][0]),
                       lo32(acc2[i][1]), hi32(acc2[i][1]) };
        #pragma unroll
        for (int j = 0; j < 4; j++) {
            int n = n0 + tn + j;
            g_pre[d][t0 + tm + i][n] = r[j] + bih[n] + bhh[n];
        }
    }
}

// ---------------------------------------------------------------------------
// Kernel 2: LSTM recurrence, 8-CTA cluster per direction. Best-measured
// configuration (round 14): all-lane h computation (lane l finishes element
// e = l>>3), one 4-byte st.async per lane to dest CTA l&7 (256 msgs x 4 B per
// dest per phase, expect_tx 1024 B), tanh.approx activations, step loop
// unrolled by 2 for compile-time buffer parity.
// ---------------------------------------------------------------------------
__global__ void __cluster_dims__(8, 1, 1) __launch_bounds__(256, 1)
lstm_kernel(const float* __restrict__ WhhF, const float* __restrict__ WhhB,
            const float* __restrict__ h0, const float* __restrict__ c0)
{
    __shared__ __align__(16) float h_sm[2][H2_];
    __shared__ __align__(8) unsigned long long mbar[2];

    const int d = blockIdx.y;
    unsigned rank;
    asm("mov.u32 %0, %%cluster_ctarank;" : "=r"(rank));

    const int tid = threadIdx.x;
    const int w = tid >> 5;          // warp 0..7
    const int l = tid & 31;          // lane
    const int ri = l >> 1;           // row-in-warp 0..15
    const int half = l & 1;          // column half
    const int q = ri >> 2;           // own gate: 0=i 1=f 2=g 3=o (= l>>3)
    const int i4 = ri & 3;           // own element within warp's 4 h-values
    const int e = l >> 3;            // element this lane FINISHES (c/h owner)
    const int grow = q * 256 + (int)rank * 32 + w * 4 + i4;   // global W row
    const float* __restrict__ Whh = d ? WhhB : WhhF;

    // Weights: 128 floats per thread = 64 packed f32x2 register pairs
    unsigned long long w2[64];
    {
        const float* wrow = Whh + (size_t)grow * H2_ + half * 128;
        #pragma unroll
        for (int i = 0; i < 32; i++) {
            ulonglong2 v = *(const ulonglong2*)(wrow + 4 * i);
            w2[2 * i] = v.x; w2[2 * i + 1] = v.y;
        }
    }

    const unsigned mb0 = (unsigned)__cvta_generic_to_shared(&mbar[0]);
    const unsigned mb1 = (unsigned)__cvta_generic_to_shared(&mbar[1]);
    if (tid == 0) {
        asm volatile("mbarrier.init.shared.b64 [%0], %1;" :: "r"(mb0), "r"(1) : "memory");
        asm volatile("mbarrier.init.shared.b64 [%0], %1;" :: "r"(mb1), "r"(1) : "memory");
        // pre-post phase 0 of both barriers (stores from steps 0 and 1)
        asm volatile("mbarrier.arrive.expect_tx.shared.b64 _, [%0], %1;" :: "r"(mb1), "r"(1024) : "memory");
        asm volatile("mbarrier.arrive.expect_tx.shared.b64 _, [%0], %1;" :: "r"(mb0), "r"(1024) : "memory");
    }
    h_sm[0][tid] = h0[d * H2_ + tid];
    const int hbase = (int)rank * 32 + w * 4;
    float cst = c0[d * H2_ + hbase + e];     // c-state for element e (8x repl)
    __syncthreads();
    // barrier init + pre-posts must be cluster-visible before any peer st.async
    asm volatile("barrier.cluster.arrive.aligned;" ::: "memory");
    asm volatile("barrier.cluster.wait.aligned;"   ::: "memory");

    const float* __restrict__ pre = &g_pre[d][0][0];
    const unsigned hs0 = (unsigned)__cvta_generic_to_shared(&h_sm[0][hbase]);
    const unsigned hs1 = (unsigned)__cvta_generic_to_shared(&h_sm[1][hbase]);
    // activation constants: g-gate (q==2) uses tanh(z); others 0.5+0.5*tanh(z/2)
    const float kmul = (q == 2) ? 1.f : 0.5f;
    const float kscale = (q == 2) ? 1.f : 0.5f;
    const float kaff = (q == 2) ? 0.f : 0.5f;
    unsigned ph0 = 0, ph1 = 0;

    // gate-gather shfl sources for element e: lanes q'*8 + 2e
    const int srcI = 2 * e;
    // hoisted per-lane remote addresses: dest CTA = l&7, slot = element e
    const int dl = l & 7;
    unsigned ra0, ra1, rb0, rb1;
    asm("mapa.shared::cluster.u32 %0, %1, %2;" : "=r"(ra0) : "r"(hs0 + e * 4u), "r"(dl));
    asm("mapa.shared::cluster.u32 %0, %1, %2;" : "=r"(ra1) : "r"(hs1 + e * 4u), "r"(dl));
    asm("mapa.shared::cluster.u32 %0, %1, %2;" : "=r"(rb0) : "r"(mb0), "r"(dl));
    asm("mapa.shared::cluster.u32 %0, %1, %2;" : "=r"(rb1) : "r"(mb1), "r"(dl));

    const bool reposter = (w == 0 && l == 0);
    const bool stg = (dl == 0);

    // one step, compile-time buffer parity
#define LSTM_STEP(T, BUF, MBC, PHC, RA_NEXT, RB_NEXT)                          \
    {                                                                          \
        float p = __ldg(pre + (size_t)(T) * H4_ + grow);                       \
        if ((T) > 0) {                                                         \
            mbar_wait(MBC, PHC); PHC ^= 1;                                     \
            if (reposter && (T) <= L_ - 3) {                                   \
                asm volatile("mbarrier.arrive.expect_tx.shared.b64 _, [%0], %1;" \
                             :: "r"(MBC), "r"(1024) : "memory");               \
            }                                                                  \
        }                                                                      \
        const float* hb = h_sm[BUF] + half * 128;                              \
        unsigned long long a0 = 0, a1 = 0, a2 = 0, a3 = 0;                     \
        _Pragma("unroll")                                                      \
        for (int i = 0; i < 16; i++) {                                         \
            ulonglong2 hv0 = *(const ulonglong2*)(hb + 8 * i);                 \
            ulonglong2 hv1 = *(const ulonglong2*)(hb + 8 * i + 4);             \
            fma2(a0, w2[4 * i + 0], hv0.x);                                    \
            fma2(a1, w2[4 * i + 1], hv0.y);                                    \
            fma2(a2, w2[4 * i + 2], hv1.x);                                    \
            fma2(a3, w2[4 * i + 3], hv1.y);                                    \
        }                                                                      \
        float s = (lo32(a0) + hi32(a0)) + (lo32(a1) + hi32(a1))                \
                + (lo32(a2) + hi32(a2)) + (lo32(a3) + hi32(a3));               \
        s += __shfl_xor_sync(0xffffffffu, s, 1);                               \
        float z = s + p;                                                       \
        float tt = tanh_ap(z * kmul);                                          \
        float act = fmaf(kscale, tt, kaff);                                    \
        float iA = __shfl_sync(0xffffffffu, act, srcI);                        \
        float fA = __shfl_sync(0xffffffffu, act, srcI + 8);                    \
        float gA = __shfl_sync(0xffffffffu, act, srcI + 16);                   \
        float oA = __shfl_sync(0xffffffffu, act, srcI + 24);                   \
        cst = fA * cst + iA * gA;                                              \
        float th = tanh_ap(cst);                                               \
        float h = oA * th;                                                     \
        if ((T) < L_ - 1) {                                                    \
            asm volatile("st.async.shared::cluster.mbarrier::complete_tx::bytes.b32 " \
                         "[%0], %1, [%2];"                                     \
                         :: "r"(RA_NEXT), "r"(__float_as_uint(h)), "r"(RB_NEXT) : "memory"); \
        }                                                                      \
        if (stg) {                                                             \
            const int pos = d ? (L_ - 1 - (T)) : (T);                          \
            g_h[d][pos][hbase + e] = h;                                        \
        }                                                                      \
    }

    for (int t = 0; t < L_; t += 2) {
        LSTM_STEP(t,     0, mb0, ph0, ra1, rb1)   // even step: read buf 0, feed buf 1
        LSTM_STEP(t + 1, 1, mb1, ph1, ra0, rb0)   // odd step:  read buf 1, feed buf 0
    }
#undef LSTM_STEP

    // all phases fully consumed by the final waits; plain exit sync
    asm volatile("barrier.cluster.arrive.aligned;" ::: "memory");
    asm volatile("barrier.cluster.wait.aligned;"   ::: "memory");
}

// ---------------------------------------------------------------------------
// Kernel 3: feats[p][tag] = concat(hf[p],hb[p]) . W_out[tag] + b_out[tag]
// ---------------------------------------------------------------------------
__global__ __launch_bounds__(256) void feats_kernel(
    const float* __restrict__ Wout, const float* __restrict__ bout)
{
    const int warp = threadIdx.x >> 5, lane = threadIdx.x & 31;
    const int p = blockIdx.x * 8 + warp;
    float x[16];
    #pragma unroll
    for (int i = 0; i < 8; i++) x[i] = g_h[0][p][lane + 32 * i];
    #pragma unroll
    for (int i = 0; i < 8; i++) x[8 + i] = g_h[1][p][lane + 32 * i];
    #pragma unroll
    for (int tag = 0; tag < T_; tag++) {
        const float* wrow = Wout + tag * (2 * H2_);
        float acc = 0.f;
        #pragma unroll
        for (int i = 0; i < 16; i++)
            acc += x[i] * wrow[(i < 8 ? 0 : 256) + lane + 32 * (i & 7)];
        #pragma unroll
        for (int o = 16; o > 0; o >>= 1) acc += __shfl_xor_sync(0xffffffffu, acc, o);
        if (lane == 0) g_feats[p][tag] = acc + bout[tag];
    }
}

// ---------------------------------------------------------------------------
// Kernel 4a: CRF chunk matrices (log-semiring parallel scan, 128 chunks x 16).
// ---------------------------------------------------------------------------
__global__ __launch_bounds__(256) void crf_chunks_kernel(
    const float* __restrict__ trans)
{
    const int warp = threadIdx.x >> 5, lane = threadIdx.x & 31;
    const int wc = blockIdx.x * 8 + warp;     // chunk id 0..127
    const int ln = (lane < T_) ? lane : 0;    // this lane's "next" state n

    float trr[T_];
    #pragma unroll
    for (int k = 0; k < T_; k++) trr[k] = trans[ln * T_ + k];

    float m[T_];
    #pragma unroll
    for (int p = 0; p < T_; p++) m[p] = (ln == p) ? 0.f : NEGI_;

    const float* ff = &g_feats[wc * CLEN_][0];
    for (int s = 0; s < CLEN_; s++) {
        const float emit = ff[s * T_ + ln];
        #pragma unroll
        for (int p = 0; p < T_; p++) {
            float v0 = __shfl_sync(0xffffffffu, m[p], 0) + trr[0];
            float v1 = __shfl_sync(0xffffffffu, m[p], 1) + trr[1];
            float v2 = __shfl_sync(0xffffffffu, m[p], 2) + trr[2];
            float v3 = __shfl_sync(0xffffffffu, m[p], 3) + trr[3];
            float v4 = __shfl_sync(0xffffffffu, m[p], 4) + trr[4];
            float v5 = __shfl_sync(0xffffffffu, m[p], 5) + trr[5];
            float mx = fmaxf(fmaxf(fmaxf(v0, v1), fmaxf(v2, v3)), fmaxf(v4, v5));
            float sum = __expf(v0 - mx) + __expf(v1 - mx) + __expf(v2 - mx)
                      + __expf(v3 - mx) + __expf(v4 - mx) + __expf(v5 - mx);
            m[p] = mx + __logf(sum) + emit;
        }
    }
    if (lane < T_) {
        #pragma unroll
        for (int p = 0; p < T_; p++) g_mats[wc][lane * T_ + p] = m[p];
    }
}

// ---------------------------------------------------------------------------
// Kernel 4b: gold score + fold chunk matrices into fv, final logsumexp.
// ---------------------------------------------------------------------------
__global__ __launch_bounds__(256) void crf_final_kernel(
    const int* __restrict__ tags, const float* __restrict__ trans,
    float* __restrict__ out)
{
    __shared__ float red[256];
    const int tid = threadIdx.x;

    // gold score
    float g = 0.f;
    for (int i = tid; i < L_; i += 256) {
        int cur = tags[i];
        int prev = (i == 0) ? START_ : tags[i - 1];
        g += trans[cur * T_ + prev] + g_feats[i][cur];
    }
    if (tid == 0) g += trans[STOP_ * T_ + tags[L_ - 1]];
    red[tid] = g;
    __syncthreads();
    for (int s = 128; s > 0; s >>= 1) {
        if (tid < s) red[tid] += red[tid + s];
        __syncthreads();
    }

    if (tid < 32) {
        const int ln = (tid < T_) ? tid : 0;
        float fv = (ln == START_) ? 0.f : NEG_;
        for (int c = 0; c < NCHUNK_; c++) {
            float r0 = g_mats[c][ln * T_ + 0], r1 = g_mats[c][ln * T_ + 1];
            float r2 = g_mats[c][ln * T_ + 2], r3 = g_mats[c][ln * T_ + 3];
            float r4 = g_mats[c][ln * T_ + 4], r5 = g_mats[c][ln * T_ + 5];
            float v0 = r0 + __shfl_sync(0xffffffffu, fv, 0);
            float v1 = r1 + __shfl_sync(0xffffffffu, fv, 1);
            float v2 = r2 + __shfl_sync(0xffffffffu, fv, 2);
            float v3 = r3 + __shfl_sync(0xffffffffu, fv, 3);
            float v4 = r4 + __shfl_sync(0xffffffffu, fv, 4);
            float v5 = r5 + __shfl_sync(0xffffffffu, fv, 5);
            float mx = fmaxf(fmaxf(fmaxf(v0, v1), fmaxf(v2, v3)), fmaxf(v4, v5));
            float sum = __expf(v0 - mx) + __expf(v1 - mx) + __expf(v2 - mx)
                      + __expf(v3 - mx) + __expf(v4 - mx) + __expf(v5 - mx);
            fv = mx + __logf(sum);
        }
        // final: logsumexp(fv + trans[STOP])
        float v = fv + trans[STOP_ * T_ + ln];
        if (tid >= T_) v = NEGI_;
        float mx = v;
        #pragma unroll
        for (int o = 4; o > 0; o >>= 1) mx = fmaxf(mx, __shfl_xor_sync(0xffu, mx, o));
        mx = __shfl_sync(0xffffffffu, mx, 0);
        float e = (tid < T_) ? __expf(v - mx) : 0.f;
        #pragma unroll
        for (int o = 4; o > 0; o >>= 1) e += __shfl_xor_sync(0xffu, e, o);
        if (tid == 0) out[0] = mx + __logf(e) - red[0];
    }
}

// ---------------------------------------------------------------------------
extern "C" void kernel_launch(void* const* d_in, const int* in_sizes, int n_in,
                              void* d_out, int out_size)
{
    const int*   sentence = (const int*)d_in[0];
    const int*   tags     = (const int*)d_in[1];
    const float* embed    = (const float*)d_in[2];
    const float* Wih_f    = (const float*)d_in[3];
    const float* Whh_f    = (const float*)d_in[4];
    const float* bih_f    = (const float*)d_in[5];
    const float* bhh_f    = (const float*)d_in[6];
    const float* Wih_b    = (const float*)d_in[7];
    const float* Whh_b    = (const float*)d_in[8];
    const float* bih_b    = (const float*)d_in[9];
    const float* bhh_b    = (const float*)d_in[10];
    const float* h0       = (const float*)d_in[11];
    const float* c0       = (const float*)d_in[12];
    const float* W_out    = (const float*)d_in[13];
    const float* b_out    = (const float*)d_in[14];
    const float* trans    = (const float*)d_in[15];
    float* out = (float*)d_out;

    gemm_pre_kernel<<<dim3(L_ / 64, H4_ / 64, 2), 256>>>(
        sentence, embed, Wih_f, bih_f, bhh_f, Wih_b, bih_b, bhh_b);
    lstm_kernel<<<dim3(8, 2), 256>>>(Whh_f, Whh_b, h0, c0);
    feats_kernel<<<L_ / 8, 256>>>(W_out, b_out);
    crf_chunks_kernel<<<NCHUNK_ / 8, 256>>>(trans);
    crf_final_kernel<<<1, 256>>>(tags, trans, out);
}